// round 6
// baseline (speedup 1.0000x reference)
#include <cuda_runtime.h>
#include <math.h>

#define DD 64
#define KK 512

typedef unsigned long long u64;

__device__ __forceinline__ u64 pk2(float a, float b) {
    u64 r; asm("mov.b64 %0,{%1,%2};" : "=l"(r) : "f"(a), "f"(b)); return r;
}
__device__ __forceinline__ void upk2(u64 v, float& a, float& b) {
    asm("mov.b64 {%0,%1},%2;" : "=f"(a), "=f"(b) : "l"(v));
}
__device__ __forceinline__ u64 fma2(u64 a, u64 b, u64 c) {
    u64 d; asm("fma.rn.f32x2 %0,%1,%2,%3;" : "=l"(d) : "l"(a), "l"(b), "l"(c)); return d;
}
__device__ __forceinline__ u64 add2(u64 a, u64 b) {
    u64 d; asm("add.rn.f32x2 %0,%1,%2;" : "=l"(d) : "l"(a), "l"(b)); return d;
}

// Reference-style squared-norm: pair-sum (j, j+32) then 32-lane binary-tree
// reduction in XLA shuffle-down pairing order, emulated serially in exact fp32.
__device__ __forceinline__ float ref_norm2(const float* __restrict__ r) {
    float a[32];
    #pragma unroll
    for (int j = 0; j < 32; j++)
        a[j] = __fadd_rn(__fmul_rn(r[j], r[j]), __fmul_rn(r[j + 32], r[j + 32]));
    #pragma unroll
    for (int j = 0; j < 16; j++) a[j] = __fadd_rn(a[j], a[j + 16]);
    #pragma unroll
    for (int j = 0; j < 8; j++)  a[j] = __fadd_rn(a[j], a[j + 8]);
    #pragma unroll
    for (int j = 0; j < 4; j++)  a[j] = __fadd_rn(a[j], a[j + 4]);
    a[0] = __fadd_rn(a[0], a[2]); a[1] = __fadd_rn(a[1], a[3]);
    return __fadd_rn(a[0], a[1]);
}

// SMEM: W [512][64] + hot w2[512] + emulated w2[512]
#define SMEM_MAIN ((KK * DD + 2 * KK) * 4)

// Rows whose hot-path top-2 dist gap is below this get the reference-emulation
// cold path. Covers hot-path noise (~5e-7) + the reference's dot-rounding
// flip zone (~1e-5 on d2 ~ 5e-7..4e-6 on dist) with margin.
#define TIE_TAU 3e-5f

__global__ __launch_bounds__(256, 1)
void sq_main(const float* __restrict__ x, const float* __restrict__ w,
             float* __restrict__ outq, float* __restrict__ outidx, int N) {
    extern __shared__ float smem[];
    float* wsh  = smem;                 // KK*DD
    float* w2sh = smem + KK * DD;       // KK (hot path)
    float* w2em = smem + KK * DD + KK;  // KK (reference-emulated)

    for (int i = threadIdx.x; i < KK * DD / 4; i += blockDim.x) {
        ((float4*)wsh)[i] = ((const float4*)w)[i];
    }
    __syncthreads();
    for (int k = threadIdx.x; k < KK; k += blockDim.x) {
        const float* r = wsh + k * DD;
        float s = 0.f;
        #pragma unroll 16
        for (int d = 0; d < DD; d++) s += r[d] * r[d];
        w2sh[k] = s;
        w2em[k] = ref_norm2(r);
    }
    __syncthreads();

    int row    = blockIdx.x * blockDim.x + threadIdx.x;
    int stride = gridDim.x * blockDim.x;

    for (; row < N; row += stride) {
        const float4* xr = (const float4*)(x + (size_t)row * DD);
        u64 xp[DD / 2];
        float x2 = 0.f;
        #pragma unroll
        for (int i = 0; i < DD / 4; i++) {
            float4 v = xr[i];
            xp[2 * i]     = pk2(v.x, v.y);
            xp[2 * i + 1] = pk2(v.z, v.w);
            x2 += v.x * v.x + v.y * v.y + v.z * v.z + v.w * v.w;
        }

        u64 accp[DD / 2];
        #pragma unroll
        for (int i = 0; i < DD / 2; i++) accp[i] = 0ull;

        float s = 0.f;
        float dist1 = -3.4e38f, dist2 = -3.4e38f;
        int   bestk = 0;

        #pragma unroll 1
        for (int k = 0; k < KK; k++) {
            const float4* wr = (const float4*)(wsh + k * DD);
            u64 a0 = 0ull, a1 = 0ull, a2 = 0ull, a3 = 0ull;
            #pragma unroll
            for (int i = 0; i < DD / 4; i++) {
                float4 wv = wr[i];
                u64 wlo = pk2(wv.x, wv.y), whi = pk2(wv.z, wv.w);
                if (i & 1) { a2 = fma2(xp[2 * i], wlo, a2); a3 = fma2(xp[2 * i + 1], whi, a3); }
                else       { a0 = fma2(xp[2 * i], wlo, a0); a1 = fma2(xp[2 * i + 1], whi, a1); }
            }
            u64 t = add2(add2(a0, a1), add2(a2, a3));
            float tl, th; upk2(t, tl, th);
            float dot = tl + th;

            float d2 = fmaxf(__fsub_rn(__fadd_rn(x2, w2sh[k]), 2.f * dot), 0.f);
            float dist = -sqrtf(d2);
            float e = __expf(dist);                // dist in [-13,0]: shift-0 softmax safe
            s += e;

            if (dist > dist1) { dist2 = dist1; dist1 = dist; bestk = k; }
            else if (dist > dist2) { dist2 = dist; }

            u64 ee = pk2(e, e);
            #pragma unroll
            for (int i = 0; i < DD / 4; i++) {
                float4 wv = wr[i];
                accp[2 * i]     = fma2(ee, pk2(wv.x, wv.y), accp[2 * i]);
                accp[2 * i + 1] = fma2(ee, pk2(wv.z, wv.w), accp[2 * i + 1]);
            }
        }

        float inv = 1.f / s;
        float4* qo = (float4*)(outq + (size_t)row * DD);
        #pragma unroll
        for (int i = 0; i < DD / 4; i++) {
            float a, b, c, d;
            upk2(accp[2 * i], a, b);
            upk2(accp[2 * i + 1], c, d);
            float4 v; v.x = a * inv; v.y = b * inv; v.z = c * inv; v.w = d * inv;
            qo[i] = v;
        }

        // Cold path (rare): bit-faithful emulation of the reference pipeline.
        //   dot  = strict sequential fp32 FMA over k=0..63 (cublas/Eigen order)
        //   w2   = reference-style tree reduce (precomputed)
        //   d2   = fl(fl(x2em + w2em) - fl(2*dot)), clamp, dist = -sqrt_rn
        //   softmax: max-subtract, correctly-rounded exp, fdiv by sum
        //   argmax: strict >, first index wins (tie-collapse matches jnp.argmax)
        if (dist1 - dist2 < TIE_TAU) {
            const float* xrow = x + (size_t)row * DD;
            float xf[DD];
            #pragma unroll
            for (int d = 0; d < DD; d++) xf[d] = xrow[d];
            float x2em = ref_norm2(xf);

            float distbuf[KK];
            float m = -3.4e38f;
            #pragma unroll 1
            for (int k = 0; k < KK; k++) {
                const float* r = wsh + k * DD;
                float acc = 0.f;
                #pragma unroll
                for (int d = 0; d < DD; d++) acc = __fmaf_rn(xf[d], r[d], acc);
                float d2 = __fsub_rn(__fadd_rn(x2em, w2em[k]), __fmul_rn(2.f, acc));
                if (d2 < 0.f) d2 = 0.f;
                float dist = -__fsqrt_rn(d2);
                distbuf[k] = dist;
                m = fmaxf(m, dist);
            }
            float ssum = 0.f;
            #pragma unroll 1
            for (int k = 0; k < KK; k++)
                ssum = __fadd_rn(ssum, (float)exp((double)__fsub_rn(distbuf[k], m)));
            float bestv = -1.f;
            int bk = 0;
            #pragma unroll 1
            for (int k = 0; k < KK; k++) {
                float e = (float)exp((double)__fsub_rn(distbuf[k], m));
                float v = __fdiv_rn(e, ssum);
                if (v > bestv) { bestv = v; bk = k; }
            }
            bestk = bk;
        }

        if (outidx) outidx[row] = (float)bestk;
    }
}

// Ortho loss: mean((norm_w @ norm_w^T)^2) - 1/K
#define OSTRIDE 65
#define SMEM_ORTHO (KK * OSTRIDE * 4)

__global__ __launch_bounds__(256)
void sq_ortho(const float* __restrict__ w, float* __restrict__ loss) {
    extern __shared__ float sm[];
    for (int idx = threadIdx.x; idx < KK * DD; idx += blockDim.x) {
        int r = idx >> 6, c = idx & 63;
        sm[r * OSTRIDE + c] = w[idx];
    }
    __syncthreads();
    for (int k = threadIdx.x; k < KK; k += blockDim.x) {
        float* r = sm + k * OSTRIDE;
        float n2 = 0.f;
        #pragma unroll 16
        for (int d = 0; d < DD; d++) n2 += r[d] * r[d];
        float inv = 1.f / fmaxf(sqrtf(n2), 1e-12f);
        #pragma unroll 16
        for (int d = 0; d < DD; d++) r[d] *= inv;
    }
    __syncthreads();

    float local = 0.f;
    int total = KK * KK;
    for (int p = blockIdx.x * blockDim.x + threadIdx.x; p < total;
         p += gridDim.x * blockDim.x) {
        int i = p >> 9, j = p & (KK - 1);
        const float* ri = sm + i * OSTRIDE;
        const float* rj = sm + j * OSTRIDE;
        float c = 0.f;
        #pragma unroll 16
        for (int d = 0; d < DD; d++) c += ri[d] * rj[d];
        local += c * c;
    }
    for (int off = 16; off > 0; off >>= 1)
        local += __shfl_down_sync(0xFFFFFFFF, local, off);
    __shared__ float red[8];
    int wid = threadIdx.x >> 5, lid = threadIdx.x & 31;
    if (lid == 0) red[wid] = local;
    __syncthreads();
    if (threadIdx.x == 0) {
        float bs = 0.f;
        for (int i = 0; i < (int)(blockDim.x >> 5); i++) bs += red[i];
        atomicAdd(loss, bs * (1.f / ((float)KK * (float)KK)));
        if (blockIdx.x == 0) atomicAdd(loss, -1.f / (float)KK);
    }
}

extern "C" void kernel_launch(void* const* d_in, const int* in_sizes, int n_in,
                              void* d_out, int out_size) {
    const float* x = (const float*)d_in[0];
    const float* w = (const float*)d_in[1];
    int N = in_sizes[0] / DD;

    float* out = (float*)d_out;
    size_t qn = (size_t)N * DD;
    float* outloss = nullptr;
    float* outidx  = nullptr;
    long long os = (long long)out_size;
    if (os >= (long long)(qn + 1 + (size_t)N)) {         // [quantized | loss | indices]
        outloss = out + qn;
        outidx  = out + qn + 1;
    } else if (os == (long long)(qn + (size_t)N)) {      // [quantized | indices]
        outidx = out + qn;
    } else if (os == (long long)(qn + 1)) {              // [quantized | loss]
        outloss = out + qn;
    }

    cudaFuncSetAttribute(sq_main,  cudaFuncAttributeMaxDynamicSharedMemorySize, SMEM_MAIN);
    cudaFuncSetAttribute(sq_ortho, cudaFuncAttributeMaxDynamicSharedMemorySize, SMEM_ORTHO);

    int grid = (N + 255) / 256;
    sq_main<<<grid, 256, SMEM_MAIN>>>(x, w, out, outidx, N);

    if (outloss) {
        cudaMemsetAsync(outloss, 0, sizeof(float));
        sq_ortho<<<128, 256, SMEM_ORTHO>>>(w, outloss);
    }
}